// round 3
// baseline (speedup 1.0000x reference)
#include <cuda_runtime.h>

#define BATCH 64
#define TT 512
#define II 512
#define HH 512
#define NCTA 128

typedef unsigned long long ull;

// ---- packed f32x2 helpers (sm_100+) ----
__device__ __forceinline__ ull pack2(float x, float y) {
    ull r; asm("mov.b64 %0, {%1, %2};" : "=l"(r) : "f"(x), "f"(y)); return r;
}
__device__ __forceinline__ void unpack2(ull v, float& x, float& y) {
    asm("mov.b64 {%0, %1}, %2;" : "=f"(x), "=f"(y) : "l"(v));
}
__device__ __forceinline__ ull ffma2(ull a, ull b, ull c) {
    ull d; asm("fma.rn.f32x2 %0, %1, %2, %3;" : "=l"(d) : "l"(a), "l"(b), "l"(c)); return d;
}
__device__ __forceinline__ ull fadd2(ull a, ull b) {
    ull d; asm("add.rn.f32x2 %0, %1, %2;" : "=l"(d) : "l"(a), "l"(b)); return d;
}

// ---- persistent device state (allocation-free) ----
__device__ float g_h[2][BATCH][HH];
__device__ unsigned int g_bar;     // zero-init; self-resets each launch

// ---------------------------------------------------------------------------
// Phase 1: xw = X @ Wx + bx + bh  (M=32768, N=512, K=512) -> mem region of out.
// 128x128x8 tile, double-buffered, As stored duplicated (ull), zero packs in
// the inner loop.
// ---------------------------------------------------------------------------
__global__ __launch_bounds__(256, 2) void gemm_xw_kernel(
    const float* __restrict__ X, const float* __restrict__ Wx,
    const float* __restrict__ bx, const float* __restrict__ bh,
    float* __restrict__ out)
{
    __shared__ ull   Asd[2][8][128];   // duplicated a: (a,a) per entry, 16KB
    __shared__ float Bs[2][8][128];    // 8KB

    const int tid = threadIdx.x;
    const int bm = blockIdx.y * 128;
    const int bn = blockIdx.x * 128;
    const int ty = tid >> 4;          // 0..15 -> 8 rows
    const int tx = tid & 15;          // 0..15 -> 8 cols

    const int arow = tid >> 1;        // 0..127
    const int akc  = (tid & 1) * 4;   // 0 or 4
    const int brow = tid >> 5;        // 0..7
    const int bcc  = (tid & 31) * 4;  // 0..124

    const float* Ag = X + (size_t)(bm + arow) * II + akc;
    const float* Bg = Wx + (size_t)brow * HH + bn + bcc;

    { // preload tile 0
        float4 av = *(const float4*)Ag;
        float4 bv = *(const float4*)Bg;
        Asd[0][akc+0][arow] = pack2(av.x, av.x);
        Asd[0][akc+1][arow] = pack2(av.y, av.y);
        Asd[0][akc+2][arow] = pack2(av.z, av.z);
        Asd[0][akc+3][arow] = pack2(av.w, av.w);
        *(float4*)&Bs[0][brow][bcc] = bv;
    }
    __syncthreads();

    ull acc[8][4];
#pragma unroll
    for (int i = 0; i < 8; i++)
#pragma unroll
        for (int j = 0; j < 4; j++) acc[i][j] = 0ull;

    const int NT = II / 8;   // 64
    for (int kt = 0; kt < NT; kt++) {
        const int cur = kt & 1;
        float4 av, bv;
        if (kt + 1 < NT) {
            av = *(const float4*)(Ag + (kt + 1) * 8);
            bv = *(const float4*)(Bg + (size_t)(kt + 1) * 8 * HH);
        }
#pragma unroll
        for (int kk = 0; kk < 8; kk++) {
            const ulonglong2* ap = (const ulonglong2*)&Asd[cur][kk][ty * 8];
            ulonglong2 a01 = ap[0], a23 = ap[1], a45 = ap[2], a67 = ap[3];
            const ulonglong2* bq = (const ulonglong2*)&Bs[cur][kk][tx * 8];
            ulonglong2 b01 = bq[0], b23 = bq[1];
            ull bp[4] = { b01.x, b01.y, b23.x, b23.y };
            ull aa[8] = { a01.x, a01.y, a23.x, a23.y, a45.x, a45.y, a67.x, a67.y };
#pragma unroll
            for (int i = 0; i < 8; i++)
#pragma unroll
                for (int j = 0; j < 4; j++) acc[i][j] = ffma2(aa[i], bp[j], acc[i][j]);
        }
        if (kt + 1 < NT) {
            const int nxt = cur ^ 1;
            __syncthreads();
            Asd[nxt][akc+0][arow] = pack2(av.x, av.x);
            Asd[nxt][akc+1][arow] = pack2(av.y, av.y);
            Asd[nxt][akc+2][arow] = pack2(av.z, av.z);
            Asd[nxt][akc+3][arow] = pack2(av.w, av.w);
            *(float4*)&Bs[nxt][brow][bcc] = bv;
            __syncthreads();
        }
    }

    const int n0 = bn + tx * 8;
    float bias[8];
#pragma unroll
    for (int j = 0; j < 8; j++) bias[j] = bx[n0 + j] + bh[n0 + j];

#pragma unroll
    for (int i = 0; i < 8; i++) {
        const int m = bm + ty * 8 + i;
        float o[8];
#pragma unroll
        for (int j = 0; j < 4; j++) unpack2(acc[i][j], o[j*2], o[j*2+1]);
        float4 v0 = make_float4(o[0]+bias[0], o[1]+bias[1], o[2]+bias[2], o[3]+bias[3]);
        float4 v1 = make_float4(o[4]+bias[4], o[5]+bias[5], o[6]+bias[6], o[7]+bias[7]);
        *(float4*)&out[(size_t)m * HH + n0]     = v0;
        *(float4*)&out[(size_t)m * HH + n0 + 4] = v1;
    }
}

// ---------------------------------------------------------------------------
// Phase 2: persistent recurrence, 128 CTAs x 256 threads.
// CTA tile: 16 batches x 16 columns.
// Thread: lane = (jq<<3)|kgl, warp = bh*4 + kgh.
//   kg = kgh*8 + kgl in [0,32)  -> k-chunk of 16
//   jq in [0,4)                 -> 4 columns (2 packed pairs)
//   bh in [0,2)                 -> 8 batches
// h stored in smem PRE-DUPLICATED: float4 = (h_k,h_k,h_{k+1},h_{k+1}),
// XOR-swizzled; zero pack instructions in the FMA loop; jq lanes broadcast.
// Reduce: shfl fold over kgl (8 lanes), then smem pass over kgh (4 warps).
// ---------------------------------------------------------------------------
#define FOLD_ROUND(M, N)                                            \
    _Pragma("unroll")                                               \
    for (int i = 0; i < (N); i++) {                                 \
        ull give = (kgl & (M)) ? v[i] : v[i + (N)];                 \
        ull got  = __shfl_xor_sync(0xFFFFFFFFu, give, (M));         \
        ull keep = (kgl & (M)) ? v[i + (N)] : v[i];                 \
        v[i] = fadd2(keep, got);                                    \
    }

extern __shared__ char rnn_smem[];

__global__ __launch_bounds__(256, 1) void rnn_kernel(
    const float* __restrict__ Wh,   // [512, 512] k-major
    float* __restrict__ out)        // mem [64,512,512] then hid [64,512]
{
    // smem layout: hdup 64KB (16 rows x 256 float4), partials 4KB
    ulonglong2* hdup = (ulonglong2*)rnn_smem;               // 4096 entries
    ull*        part = (ull*)(rnn_smem + 65536);            // 8 warps x 32 lanes x 2

    const int tid = threadIdx.x;
    const int kgl = tid & 7;
    const int jq  = (tid >> 3) & 3;
    const int kgh = (tid >> 5) & 3;
    const int bh  = tid >> 7;
    const int kg  = kgh * 8 + kgl;
    const int warpid = tid >> 5;
    const int lane   = tid & 31;

    const int jbase = (blockIdx.x & 31) * 16;
    const int bbase = (blockIdx.x >> 5) * 16;
    const int j0 = jbase + jq * 4;

    // Wh slab -> registers as packed j-pairs
    ull w2[16][2];
#pragma unroll
    for (int kl = 0; kl < 16; kl++) {
        float4 w = *(const float4*)&Wh[(size_t)(kg * 16 + kl) * HH + j0];
        w2[kl][0] = pack2(w.x, w.y);
        w2[kl][1] = pack2(w.z, w.w);
    }

    // final-stage mapping (tid < 64): slot s = tid
    const int s = tid;
    const int fbh  = (s >> 5) & 1;
    const int floc = (s >> 2) & 7;
    const int fjq  = s & 3;
    const int fb   = bbase + fbh * 8 + floc;
    const int fj   = jbase + fjq * 4;
    const int frev = ((floc & 1) << 2) | (floc & 2) | ((floc >> 2) & 1);   // bitrev3
    const int flane = (fjq << 3) | frev;

    float* mem = out;
    float* hid = out + (size_t)BATCH * TT * HH;

    for (int t = 0; t < TT; t++) {
        float4 xwv;
        if (tid < 64)
            xwv = *(const float4*)&mem[((size_t)fb * TT + t) * HH + fj];

        ull acc[8][2];
#pragma unroll
        for (int b = 0; b < 8; b++) { acc[b][0] = 0ull; acc[b][1] = 0ull; }

        if (t > 0) {
            // stage h: L2 -> smem, duplicating each value, swizzled
            const float2* gh = (const float2*)&g_h[t & 1][bbase][0];
#pragma unroll
            for (int n = 0; n < 16; n++) {
                int e = tid + n * 256;
                int row = e >> 8;
                int u   = e & 255;
                float2 hv = __ldcg(gh + e);
                ulonglong2 dv;
                dv.x = pack2(hv.x, hv.x);
                dv.y = pack2(hv.y, hv.y);
                hdup[(row << 8) + (u ^ ((u >> 3) & 7))] = dv;
            }
            __syncthreads();

#pragma unroll
            for (int b = 0; b < 8; b++) {
                const ulonglong2* hrow = hdup + (((bh * 8 + b) << 8) + kg * 8);
#pragma unroll
                for (int i = 0; i < 8; i++) {
                    ulonglong2 hv = hrow[i ^ kgl];
                    acc[b][0] = ffma2(hv.x, w2[2*i  ][0], acc[b][0]);
                    acc[b][1] = ffma2(hv.x, w2[2*i  ][1], acc[b][1]);
                    acc[b][0] = ffma2(hv.y, w2[2*i+1][0], acc[b][0]);
                    acc[b][1] = ffma2(hv.y, w2[2*i+1][1], acc[b][1]);
                }
            }
        }

        // intra-warp fold over the 8 kgl lanes (16 -> 2 ull per lane)
        ull v[16];
#pragma unroll
        for (int b = 0; b < 8; b++) { v[b*2+0] = acc[b][0]; v[b*2+1] = acc[b][1]; }
        FOLD_ROUND(1, 8)
        FOLD_ROUND(2, 4)
        FOLD_ROUND(4, 2)

        // cross-warp partials (sum over kgh happens in the final stage)
        ull* pdst = part + ((warpid << 5) + lane) * 2;
        pdst[0] = v[0];
        pdst[1] = v[1];
        __syncthreads();

        if (tid < 64) {
            ull s0 = 0ull, s1 = 0ull;
#pragma unroll
            for (int g = 0; g < 4; g++) {
                const ull* p = part + ((((fbh * 4 + g) << 5) + flane) << 1);
                s0 = fadd2(s0, p[0]);
                s1 = fadd2(s1, p[1]);
            }
            float a0, a1, a2, a3;
            unpack2(s0, a0, a1);
            unpack2(s1, a2, a3);
            float4 val;
            val.x = tanhf(xwv.x + a0);
            val.y = tanhf(xwv.y + a1);
            val.z = tanhf(xwv.z + a2);
            val.w = tanhf(xwv.w + a3);
            *(float4*)&mem[((size_t)fb * TT + t) * HH + fj] = val;
            *(float4*)&g_h[(t + 1) & 1][fb][fj] = val;
            if (t == TT - 1) *(float4*)&hid[(size_t)fb * HH + fj] = val;
            __threadfence();
        }

        if (t < TT - 1) {
            __syncthreads();
            if (tid == 0) {
                atomicAdd(&g_bar, 1u);
                const unsigned int target = (unsigned int)(t + 1) * NCTA;
                while (*(volatile unsigned int*)&g_bar < target) { }
                __threadfence();
            }
            __syncthreads();
        }
    }

    // self-reset barrier counter for the next launch / graph replay
    __syncthreads();
    if (tid == 0) {
        unsigned int old = atomicAdd(&g_bar, 1u);
        if (old == (unsigned int)(TT - 1) * NCTA + (NCTA - 1)) {
            atomicExch(&g_bar, 0u);
        }
    }
}

// ---------------------------------------------------------------------------
extern "C" void kernel_launch(void* const* d_in, const int* in_sizes, int n_in,
                              void* d_out, int out_size) {
    const float* x  = (const float*)d_in[0];  // [64, 512, 512]
    const float* Wx = (const float*)d_in[1];  // [512, 512]
    const float* Wh = (const float*)d_in[2];  // [512, 512]
    const float* bx = (const float*)d_in[3];  // [1, 512]
    const float* bh = (const float*)d_in[4];  // [1, 512]
    float* out = (float*)d_out;

    cudaFuncSetAttribute(rnn_kernel, cudaFuncAttributeMaxDynamicSharedMemorySize,
                         65536 + 4096);

    dim3 ggrid(HH / 128, (BATCH * TT) / 128);   // (4, 256)
    gemm_xw_kernel<<<ggrid, 256>>>(x, Wx, bx, bh, out);

    rnn_kernel<<<NCTA, 256, 65536 + 4096>>>(Wh, out);
}